// round 7
// baseline (speedup 1.0000x reference)
#include <cuda_runtime.h>
#include <cuda_bf16.h>
#include <mma.h>
#include <cstdint>
#include <math.h>
using namespace nvcuda;
typedef __nv_bfloat16 bf16;

#define BS 2
#define DD 512
#define NN 65536
#define RR 64
#define EPSF 1e-6f

__device__ __align__(16) bf16 g_xu_h[(size_t)BS*DD*NN], g_xu_l[(size_t)BS*DD*NN]; // x unclamped [d][n]
__device__ __align__(16) bf16 g_xc_h[(size_t)BS*DD*NN], g_xc_l[(size_t)BS*DD*NN]; // x clamped   [d][n]
__device__ __align__(16) bf16 g_bt_h[BS*RR*DD], g_bt_l[BS*RR*DD];                 // b^T [r][d]
__device__ __align__(16) bf16 g_bn_h[BS*DD*RR], g_bn_l[BS*DD*RR];                 // b [d][r]
__device__ __align__(16) float g_c[(size_t)BS*NN*RR];
__device__ float g_b0[BS*DD*RR], g_b1[BS*DD*RR];
__device__ float g_BtB[BS*RR*RR], g_CtC[BS*RR*RR], g_numB[BS*DD*RR];
__device__ __forceinline__ float* bsel(int s){ return s ? g_b1 : g_b0; }

__device__ __forceinline__ void split2(float v, unsigned short& h, unsigned short& l){
    bf16 hb = __float2bfloat16_rn(v);
    bf16 lb = __float2bfloat16_rn(v - __bfloat162float(hb));
    h = __bfloat16_as_ushort(hb); l = __bfloat16_as_ushort(lb);
}
__device__ __forceinline__ uint32_t pk(unsigned short a, unsigned short b){ return (uint32_t)a | ((uint32_t)b << 16); }
__device__ __forceinline__ uint32_t smem_u32(const void* p){
    uint32_t a; asm("{ .reg .u64 t; cvta.to.shared.u64 t, %1; cvt.u32.u64 %0, t; }" : "=r"(a) : "l"(p)); return a;
}
__device__ __forceinline__ void cpa16(uint32_t s, const void* g){
    asm volatile("cp.async.cg.shared.global [%0], [%1], 16;" :: "r"(s), "l"(g) : "memory");
}
#define CPCOMMIT() asm volatile("cp.async.commit_group;" ::: "memory")
#define CPWAIT1()  asm volatile("cp.async.wait_group 1;" ::: "memory")
#define CPWAIT0()  asm volatile("cp.async.wait_group 0;" ::: "memory")

// smem map (bytes):
// phase A: A stages 2x20480 @0, B stages 2x10240 @40960; overlays: Ct f32[128][72]@0,
//   BtB@40960(16KB), csm f32[128][65]@61440(33280)
// CS (c' splits, [r=64][n=128] stride 136): hi@61440(17408), lo@78848(17408) -> 96256
// phase B: x/b stages @0; Snb/Sx staging @40960
#define SMEMG 96256
#define CS_H 61440
#define CS_L 78848

typedef wmma::fragment<wmma::accumulator,16,16,16,float> AccFrag;
typedef wmma::fragment<wmma::matrix_a,16,16,16,bf16,wmma::row_major> AFragR;
typedef wmma::fragment<wmma::matrix_a,16,16,16,bf16,wmma::col_major> AFragC;
typedef wmma::fragment<wmma::matrix_b,16,16,16,bf16,wmma::row_major> BFragR;
typedef wmma::fragment<wmma::matrix_b,16,16,16,bf16,wmma::col_major> BFragC;

// ---- phase A chunk load: A col-major source [d][n] (32 k-rows x 128), B [r][d] (64 x 32)
__device__ __forceinline__ void issueA(uint32_t sb, int st,
    const bf16* Ah, const bf16* Al, size_t lda, const bf16* Bh, const bf16* Bl, size_t ldb, size_t k0){
    int t = threadIdx.x;
    uint32_t ab = sb + st*20480, bb = sb + 40960 + st*10240;
    #pragma unroll
    for (int u = 0; u < 2; u++){
        int idx = t + u*256, r = idx >> 4, sg = (idx & 15)*8;
        cpa16(ab +        (r*136 + sg)*2, Ah + (k0+r)*lda + sg);
        cpa16(ab + 8704 + (r*136 + sg)*2, Al + (k0+r)*lda + sg);
    }
    { int r = t >> 2, sg = (t & 3)*8;
      cpa16(bb +        (r*40 + sg)*2, Bh + r*ldb + k0 + sg);
      cpa16(bb + 5120 + (r*40 + sg)*2, Bl + r*ldb + k0 + sg);
    }
    CPCOMMIT();
}

__device__ __forceinline__ void gemmA(const bf16* Ah, const bf16* Al, size_t lda,
    const bf16* Bh, const bf16* Bl, size_t ldb, char* sm, uint32_t sb, AccFrag (&acc)[2][2]){
    int wid = threadIdx.x >> 5, wm = wid >> 1, wn = wid & 1;
    #pragma unroll
    for (int i = 0; i < 2; i++)
        #pragma unroll
        for (int j = 0; j < 2; j++) wmma::fill_fragment(acc[i][j], 0.0f);
    issueA(sb, 0, Ah, Al, lda, Bh, Bl, ldb, 0);
    for (int kc = 0; kc < 16; kc++){
        int cur = kc & 1;
        if (kc < 15){ issueA(sb, cur^1, Ah, Al, lda, Bh, Bl, ldb, (size_t)(kc+1)*32); CPWAIT1(); }
        else CPWAIT0();
        __syncthreads();
        bf16* As = (bf16*)(sm + cur*20480);
        bf16* Bs = (bf16*)(sm + 40960 + cur*10240);
        #pragma unroll
        for (int k = 0; k < 2; k++){
            BFragC fbh[2], fbl[2];
            #pragma unroll
            for (int j = 0; j < 2; j++){
                wmma::load_matrix_sync(fbh[j], Bs + (wn*32+j*16)*40 + k*16, 40);
                wmma::load_matrix_sync(fbl[j], Bs + 2560 + (wn*32+j*16)*40 + k*16, 40);
            }
            AFragC fah[2], fal[2];
            #pragma unroll
            for (int i = 0; i < 2; i++){
                wmma::load_matrix_sync(fah[i], As + (k*16)*136 + wm*32+i*16, 136);
                wmma::load_matrix_sync(fal[i], As + 4352 + (k*16)*136 + wm*32+i*16, 136);
            }
            #pragma unroll
            for (int i = 0; i < 2; i++)
                #pragma unroll
                for (int j = 0; j < 2; j++){
                    wmma::mma_sync(acc[i][j], fah[i], fbh[j], acc[i][j]);
                    wmma::mma_sync(acc[i][j], fah[i], fbl[j], acc[i][j]);
                    wmma::mma_sync(acc[i][j], fal[i], fbh[j], acc[i][j]);
                }
        }
        __syncthreads();
    }
}

// ---- prep / normb / zero / btb / bupdate ----
__global__ void __launch_bounds__(256) k_prep(const float* __restrict__ x){
    size_t base = ((size_t)blockIdx.x*256 + threadIdx.x)*16;
    #pragma unroll
    for (int q = 0; q < 4; q++){
        size_t o = base + q*4;
        float4 v = *(const float4*)(x + o);
        unsigned short h[4], l[4];
        split2(v.x,h[0],l[0]); split2(v.y,h[1],l[1]); split2(v.z,h[2],l[2]); split2(v.w,h[3],l[3]);
        *(uint2*)(g_xu_h + o) = make_uint2(pk(h[0],h[1]), pk(h[2],h[3]));
        *(uint2*)(g_xu_l + o) = make_uint2(pk(l[0],l[1]), pk(l[2],l[3]));
        split2(fmaxf(v.x,EPSF),h[0],l[0]); split2(fmaxf(v.y,EPSF),h[1],l[1]);
        split2(fmaxf(v.z,EPSF),h[2],l[2]); split2(fmaxf(v.w,EPSF),h[3],l[3]);
        *(uint2*)(g_xc_h + o) = make_uint2(pk(h[0],h[1]), pk(h[2],h[3]));
        *(uint2*)(g_xc_l + o) = make_uint2(pk(l[0],l[1]), pk(l[2],l[3]));
    }
}

__global__ void __launch_bounds__(128) k_normb(const float* __restrict__ bases){
    int bs = blockIdx.x >> 6, r = blockIdx.x & 63, tid = threadIdx.x;
    __shared__ float red[128];
    float s = 0.f;
    for (int d = tid; d < DD; d += 128){ float v = bases[(bs*DD+d)*RR + r]; s += v*v; }
    red[tid] = s; __syncthreads();
    for (int o = 64; o > 0; o >>= 1){ if (tid < o) red[tid] += red[tid+o]; __syncthreads(); }
    float inv = 1.f / fmaxf(sqrtf(red[0]), 1e-12f);
    for (int d = tid; d < DD; d += 128){
        float v = bases[(bs*DD+d)*RR + r] * inv;
        g_b0[(bs*DD+d)*RR + r] = v;
        unsigned short h, l; split2(v, h, l);
        g_bt_h[(bs*RR+r)*DD + d] = __ushort_as_bfloat16(h);
        g_bt_l[(bs*RR+r)*DD + d] = __ushort_as_bfloat16(l);
    }
}

__global__ void k_zero(){
    int i = blockIdx.x*256 + threadIdx.x;
    if (i < BS*RR*RR){ g_BtB[i] = 0.f; g_CtC[i] = 0.f; }
    if (i < BS*DD*RR) g_numB[i] = 0.f;
}

__global__ void __launch_bounds__(256) k_btb(int sel){
    __shared__ float bsh[64][65];
    int bs = blockIdx.y, d0 = blockIdx.x*64, tid = threadIdx.x;
    const float* bb = bsel(sel) + bs*DD*RR + d0*RR;
    for (int i = tid*4; i < 4096; i += 1024){
        float4 v = *(const float4*)(bb + i);
        int d = i >> 6, r = i & 63;
        bsh[d][r]=v.x; bsh[d][r+1]=v.y; bsh[d][r+2]=v.z; bsh[d][r+3]=v.w;
    }
    __syncthreads();
    int r = tid & 63, sq = (tid >> 6)*16;
    float acc[16];
    #pragma unroll
    for (int j = 0; j < 16; j++) acc[j] = 0.f;
    for (int d = 0; d < 64; d++){
        float br = bsh[d][r];
        #pragma unroll
        for (int j = 0; j < 16; j++) acc[j] = fmaf(br, bsh[d][sq+j], acc[j]);
    }
    float* o = g_BtB + bs*RR*RR + r*RR + sq;
    #pragma unroll
    for (int j = 0; j < 16; j++) atomicAdd(&o[j], acc[j]);
}

__global__ void __launch_bounds__(128) k_bupdate(int selIn, int selOut){
    int r = blockIdx.x, bs = blockIdx.y, tid = threadIdx.x;
    __shared__ float ctcCol[64], red[128];
    const float* bin = bsel(selIn) + bs*DD*RR;
    float* bout = bsel(selOut) + bs*DD*RR;
    const float* nb = g_numB + bs*DD*RR;
    if (tid < 64) ctcCol[tid] = g_CtC[bs*RR*RR + tid*RR + r];
    __syncthreads();
    float v[4], ss = 0.f;
    #pragma unroll
    for (int q = 0; q < 4; q++){
        int d = tid + q*128; const float* brow = bin + d*RR;
        float den = EPSF;
        #pragma unroll 8
        for (int s = 0; s < RR; s++) den = fmaf(brow[s], ctcCol[s], den);
        float t = fmaxf(brow[r] * nb[d*RR + r] / den, EPSF);
        v[q] = t; ss += t*t;
    }
    red[tid] = ss; __syncthreads();
    for (int o = 64; o > 0; o >>= 1){ if (tid < o) red[tid] += red[tid+o]; __syncthreads(); }
    float inv = 1.f / fmaxf(sqrtf(red[0]), 1e-12f);
    #pragma unroll
    for (int q = 0; q < 4; q++){
        int d = tid + q*128;
        float w = v[q] * inv;
        bout[d*RR + r] = w;
        unsigned short h, l; split2(w, h, l);
        g_bt_h[(bs*RR+r)*DD + d] = __ushort_as_bfloat16(h);
        g_bt_l[(bs*RR+r)*DD + d] = __ushort_as_bfloat16(l);
        g_bn_h[(bs*DD+d)*RR + r] = __ushort_as_bfloat16(h);
        g_bn_l[(bs*DD+d)*RR + r] = __ushort_as_bfloat16(l);
    }
}

// ---- mega kernel: numC + epilogue (+numB | +x_hat) ----
// MODE 0: coef init softmax. MODE 1: MU step (c', CtC, numB). MODE 2: final (c_new, x_hat).
template<int MODE>
__global__ void __launch_bounds__(256) k_cmma(float* __restrict__ out, int clampc){
    extern __shared__ char sm[];
    uint32_t sb = smem_u32(sm);
    int bs = blockIdx.y, n0 = blockIdx.x*128, tid = threadIdx.x;
    const bf16* xh = (MODE==0 ? g_xu_h : g_xc_h) + (size_t)bs*DD*NN + n0;
    const bf16* xl = (MODE==0 ? g_xu_l : g_xc_l) + (size_t)bs*DD*NN + n0;
    float* csm = (float*)(sm + CS_H);

    if (MODE != 0){
        size_t cbase = ((size_t)bs*NN + n0)*RR;
        for (int i = tid; i < 2048; i += 256){
            int n = i >> 4, r4 = (i & 15)*4;
            float4 v = *(const float4*)(g_c + cbase + n*RR + r4);
            if (clampc){ v.x=fmaxf(v.x,EPSF); v.y=fmaxf(v.y,EPSF); v.z=fmaxf(v.z,EPSF); v.w=fmaxf(v.w,EPSF); }
            csm[n*65+r4]=v.x; csm[n*65+r4+1]=v.y; csm[n*65+r4+2]=v.z; csm[n*65+r4+3]=v.w;
        }
    }
    AccFrag acc[2][2];
    gemmA(xh, xl, NN, g_bt_h + bs*RR*DD, g_bt_l + bs*RR*DD, DD, sm, sb, acc);
    {   // store acc -> Ct
        float* Ct = (float*)sm;
        int wid = tid >> 5, wm = wid >> 1, wn = wid & 1;
        #pragma unroll
        for (int i = 0; i < 2; i++)
            #pragma unroll
            for (int j = 0; j < 2; j++)
                wmma::store_matrix_sync(Ct + (wm*32+i*16)*72 + wn*32+j*16, acc[i][j], 72, wmma::mem_row_major);
    }
    float* Ct = (float*)sm;
    float* Bt = (float*)(sm + 40960);
    if (MODE != 0)
        for (int i = tid; i < RR*RR; i += 256) Bt[i] = g_BtB[bs*RR*RR + i];
    __syncthreads();

    int n = tid >> 1, h = tid & 1;
    size_t crow = ((size_t)bs*NN + n0 + n)*RR;
    if (MODE == 0){
        float v[32], m = -1e30f;
        #pragma unroll
        for (int j = 0; j < 32; j++){ v[j] = Ct[n*72 + h*32 + j]; m = fmaxf(m, v[j]); }
        m = fmaxf(m, __shfl_xor_sync(0xffffffffu, m, 1));
        float s = 0.f;
        #pragma unroll
        for (int j = 0; j < 32; j++){ v[j] = __expf(v[j]-m); s += v[j]; }
        s += __shfl_xor_sync(0xffffffffu, s, 1);
        float inv = 1.f/s;
        #pragma unroll
        for (int j4 = 0; j4 < 32; j4 += 4)
            *(float4*)(g_c + crow + h*32 + j4) = make_float4(v[j4]*inv, v[j4+1]*inv, v[j4+2]*inv, v[j4+3]*inv);
        return;
    }

    // denC + c' (in place into Ct); MODE1 also writes g_c
    float den[32];
    #pragma unroll
    for (int j = 0; j < 32; j++) den[j] = 0.f;
    #pragma unroll 8
    for (int s = 0; s < 64; s++){
        float cv = csm[n*65 + s];
        const float* row = &Bt[s*64 + h*32];
        #pragma unroll
        for (int j = 0; j < 32; j++) den[j] = fmaf(cv, row[j], den[j]);
    }
    #pragma unroll
    for (int j4 = 0; j4 < 32; j4 += 4){
        float cp[4];
        #pragma unroll
        for (int t = 0; t < 4; t++){
            int j = j4 + t;
            cp[t] = csm[n*65 + h*32 + j] * Ct[n*72 + h*32 + j] / (den[j] + EPSF);
            Ct[n*72 + h*32 + j] = cp[t];
        }
        if (MODE == 1)
            *(float4*)(g_c + crow + h*32 + j4) = make_float4(cp[0], cp[1], cp[2], cp[3]);
    }
    __syncthreads();   // csm dead; Ct holds c'

    // build CS = bf16 splits of c'^T [r][n] stride 136 (overwrites csm area)
    bf16* CSh = (bf16*)(sm + CS_H);
    bf16* CSl = (bf16*)(sm + CS_L);
    #pragma unroll
    for (int q = 0; q < 8; q++){
        int e = tid + q*256, r = e >> 5, n4 = (e & 31)*4;
        unsigned short hh[4], ll[4];
        #pragma unroll
        for (int i = 0; i < 4; i++) split2(Ct[(n4+i)*72 + r], hh[i], ll[i]);
        *(uint2*)(CSh + r*136 + n4) = make_uint2(pk(hh[0],hh[1]), pk(hh[2],hh[3]));
        *(uint2*)(CSl + r*136 + n4) = make_uint2(pk(ll[0],ll[1]), pk(ll[2],ll[3]));
    }
    if (MODE == 1){  // CtC partials
        int r = tid & 63, q = tid >> 6;
        float ctc[16];
        #pragma unroll
        for (int j = 0; j < 16; j++) ctc[j] = 0.f;
        for (int nn2 = 0; nn2 < 128; nn2++){
            float cr = Ct[nn2*72 + r];
            const float* row = &Ct[nn2*72 + q*16];
            #pragma unroll
            for (int j = 0; j < 16; j++) ctc[j] = fmaf(cr, row[j], ctc[j]);
        }
        float* gout = g_CtC + bs*RR*RR + r*RR + q*16;
        #pragma unroll
        for (int j = 0; j < 16; j++) atomicAdd(&gout[j], ctc[j]);
    }
    __syncthreads();   // Ct dead; stages and staging area free

    int wid = tid >> 5;
    if (MODE == 1){
        // phase B: numB += xc[d][n-tile] * c'[n-tile][r], 16 d-chunks, L2-hot x re-read
        const bf16* xch = g_xc_h + (size_t)bs*DD*NN + n0;
        const bf16* xcl = g_xc_l + (size_t)bs*DD*NN + n0;
        float* Snb = (float*)(sm + 40960);
        int wd = wid & 1, wr = wid >> 1;
        // prefetch chunk 0
        {   uint32_t ab = sb;
            #pragma unroll
            for (int u = 0; u < 2; u++){
                int idx = tid + u*256, r = idx >> 4, sg = (idx & 15)*8;
                cpa16(ab +        (r*136 + sg)*2, xch + (size_t)r*NN + sg);
                cpa16(ab + 8704 + (r*136 + sg)*2, xcl + (size_t)r*NN + sg);
            }
            CPCOMMIT();
        }
        for (int kc = 0; kc < 16; kc++){
            int cur = kc & 1;
            if (kc < 15){
                uint32_t ab = sb + (cur^1)*17408;
                #pragma unroll
                for (int u = 0; u < 2; u++){
                    int idx = tid + u*256, r = idx >> 4, sg = (idx & 15)*8;
                    cpa16(ab +        (r*136 + sg)*2, xch + (size_t)((kc+1)*32 + r)*NN + sg);
                    cpa16(ab + 8704 + (r*136 + sg)*2, xcl + (size_t)((kc+1)*32 + r)*NN + sg);
                }
                CPCOMMIT(); CPWAIT1();
            } else CPWAIT0();
            __syncthreads();
            bf16* As = (bf16*)(sm + cur*17408);
            AccFrag anb; wmma::fill_fragment(anb, 0.0f);
            #pragma unroll
            for (int ks = 0; ks < 8; ks++){
                AFragR fah, fal; BFragC fbh, fbl;
                wmma::load_matrix_sync(fah, As + (wd*16)*136 + ks*16, 136);
                wmma::load_matrix_sync(fal, As + 4352 + (wd*16)*136 + ks*16, 136);
                wmma::load_matrix_sync(fbh, CSh + (wr*16)*136 + ks*16, 136);
                wmma::load_matrix_sync(fbl, CSl + (wr*16)*136 + ks*16, 136);
                wmma::mma_sync(anb, fah, fbh, anb);
                wmma::mma_sync(anb, fah, fbl, anb);
                wmma::mma_sync(anb, fal, fbh, anb);
            }
            wmma::store_matrix_sync(Snb + (wd*16)*64 + wr*16, anb, 64, wmma::mem_row_major);
            __syncthreads();
            float* nb = g_numB + bs*DD*RR + kc*32*RR;
            #pragma unroll
            for (int q = 0; q < 8; q++){
                int e = tid + q*256;
                atomicAdd(&nb[e], Snb[e]);
            }
            __syncthreads();
        }
    } else {
        // MODE 2 phase B': x_hat[d][n-tile] = b[d][r] * c_new[n-tile][r]^T, 16 d-chunks
        const bf16* bh2 = g_bn_h + (size_t)bs*DD*RR;
        const bf16* bl2 = g_bn_l + (size_t)bs*DD*RR;
        float* Sx = (float*)(sm + 40960);
        int wd = wid & 1, wq = wid >> 1;
        {   uint32_t ab = sb;
            int r = tid >> 3, sg = (tid & 7)*8;
            cpa16(ab +        (r*72 + sg)*2, bh2 + (size_t)r*RR + sg);
            cpa16(ab + 4608 + (r*72 + sg)*2, bl2 + (size_t)r*RR + sg);
            CPCOMMIT();
        }
        for (int kc = 0; kc < 16; kc++){
            int cur = kc & 1;
            if (kc < 15){
                uint32_t ab = sb + (cur^1)*9216;
                int r = tid >> 3, sg = (tid & 7)*8;
                cpa16(ab +        (r*72 + sg)*2, bh2 + (size_t)((kc+1)*32 + r)*RR + sg);
                cpa16(ab + 4608 + (r*72 + sg)*2, bl2 + (size_t)((kc+1)*32 + r)*RR + sg);
                CPCOMMIT(); CPWAIT1();
            } else CPWAIT0();
            __syncthreads();
            bf16* As = (bf16*)(sm + cur*9216);
            AccFrag ax[2];
            wmma::fill_fragment(ax[0], 0.0f); wmma::fill_fragment(ax[1], 0.0f);
            #pragma unroll
            for (int ks = 0; ks < 4; ks++){
                AFragR fah, fal;
                wmma::load_matrix_sync(fah, As + (wd*16)*72 + ks*16, 72);
                wmma::load_matrix_sync(fal, As + 2304 + (wd*16)*72 + ks*16, 72);
                #pragma unroll
                for (int j = 0; j < 2; j++){
                    BFragR fbh, fbl;
                    wmma::load_matrix_sync(fbh, CSh + (ks*16)*136 + wq*32 + j*16, 136);
                    wmma::load_matrix_sync(fbl, CSl + (ks*16)*136 + wq*32 + j*16, 136);
                    wmma::mma_sync(ax[j], fah, fbh, ax[j]);
                    wmma::mma_sync(ax[j], fah, fbl, ax[j]);
                    wmma::mma_sync(ax[j], fal, fbh, ax[j]);
                }
            }
            #pragma unroll
            for (int j = 0; j < 2; j++)
                wmma::store_matrix_sync(Sx + (wd*16)*128 + wq*32 + j*16, ax[j], 128, wmma::mem_row_major);
            __syncthreads();
            #pragma unroll
            for (int q = 0; q < 4; q++){
                int e = tid + q*256, row = e >> 5, c4 = (e & 31)*4;
                float4 v = *(const float4*)(Sx + row*128 + c4);
                *(float4*)(out + (size_t)(bs*DD + kc*32 + row)*NN + n0 + c4) = v;
            }
            __syncthreads();
        }
    }
}

// ---------- orchestration ----------
extern "C" void kernel_launch(void* const* d_in, const int* in_sizes, int n_in,
                              void* d_out, int out_size){
    const float* x = (const float*)d_in[0];
    const float* bases = (const float*)d_in[1];
    float* out = (float*)d_out;

    cudaFuncSetAttribute(k_cmma<0>, cudaFuncAttributeMaxDynamicSharedMemorySize, SMEMG);
    cudaFuncSetAttribute(k_cmma<1>, cudaFuncAttributeMaxDynamicSharedMemorySize, SMEMG);
    cudaFuncSetAttribute(k_cmma<2>, cudaFuncAttributeMaxDynamicSharedMemorySize, SMEMG);

    k_prep<<<16384, 256>>>(x);
    k_normb<<<BS*RR, 128>>>(bases);
    int sel = 0;
    k_cmma<0><<<dim3(NN/128, BS), 256, SMEMG>>>(nullptr, 0);
    for (int step = 0; step < 6; step++){
        k_zero<<<256, 256>>>();
        k_btb<<<dim3(8, BS), 256>>>(sel);
        k_cmma<1><<<dim3(NN/128, BS), 256, SMEMG>>>(nullptr, step > 0 ? 1 : 0);
        k_bupdate<<<dim3(RR, BS), 128>>>(sel, 1 - sel);
        sel = 1 - sel;
    }
    k_zero<<<256, 256>>>();
    k_btb<<<dim3(8, BS), 256>>>(sel);
    k_cmma<2><<<dim3(NN/128, BS), 256, SMEMG>>>(out, 1);
}